// round 3
// baseline (speedup 1.0000x reference)
#include <cuda_runtime.h>
#include <cuda_bf16.h>

// Problem constants (fixed for RoIPointPool3d_23845658427905)
#define Bn 4
#define Nn 16384
#define Mn 128
#define Cn 128
#define Sn 512
#define ROW (3 + Cn)          // 131 floats per pooled row
#define NWORDS (Nn / 32)      // 512 ballot words per box
#define NT 512                // threads per block (one block per box)
#define NWARP (NT / 32)       // 16

// Fused kernel: one block per (batch, box).
//  Phase 1: warp-parallel point-in-rotated-box ballots -> shared bitmask
//  Phase 2: block scan of popcounts -> first-come-ordered index compaction
//  Phase 3: warp-per-row vectorized gather (float4) + staged coalesced row writes
__global__ __launch_bounds__(NT, 2) void roipool_kernel(
    const float* __restrict__ points,   // (B, N, 3)
    const float* __restrict__ feats,    // (B, N, C)
    const float* __restrict__ boxes,    // (B, M, 7)
    float* __restrict__ out,            // (B, M, S, 131) [+ (B,M) flags]
    int write_flags)
{
    __shared__ unsigned s_words[NWORDS];    // in-box bitmask
    __shared__ int s_table[Sn];             // first min(cnt,S) in-box point indices
    __shared__ int s_idx[Sn];               // resolved sample index per row (-1 if empty)
    __shared__ int s_warpSum[16];
    __shared__ int s_total;
    // per-warp double-buffered row staging: 33 float4 = 132 floats
    // layout per row: [0..127] = features, [128..130] = point xyz
    __shared__ float4 s_stage[NWARP][2][33];

    const int bm   = blockIdx.x;            // 0 .. B*M-1
    const int b    = bm >> 7;               // / M (M = 128)
    const int tid  = threadIdx.x;
    const int lane = tid & 31;
    const int wid  = tid >> 5;

    // ---- box parameters ----
    const float* box = boxes + bm * 7;
    const float cx = box[0];
    const float cy = box[1];
    const float dx = box[3], dy = box[4], dz = box[5];
    const float rz = box[6];
    const float cz = __fadd_rn(box[2], __fmul_rn(0.5f, dz));
    const float hx = __fmul_rn(0.5f, dx);
    const float hy = __fmul_rn(0.5f, dy);
    const float hz = __fmul_rn(0.5f, dz);
    const double nrz = -(double)rz;
    const float cosa = (float)cos(nrz);
    const float sina = (float)sin(nrz);

    const float* pts = points + (size_t)b * Nn * 3;
    const float* fb  = feats  + (size_t)b * Nn * Cn;
    const float4* fb4 = (const float4*)fb;

    // ---- Phase 1: ballots (no block syncs, pipelined) ----
    #pragma unroll 4
    for (int W = wid; W < NWORDS; W += NWARP) {
        const int i = W * 32 + lane;
        const float px = pts[i * 3 + 0];
        const float py = pts[i * 3 + 1];
        const float pz = pts[i * 3 + 2];
        const float sx = __fsub_rn(px, cx);
        const float sy = __fsub_rn(py, cy);
        const float lx = __fsub_rn(__fmul_rn(sx, cosa), __fmul_rn(sy, sina));
        const float ly = __fadd_rn(__fmul_rn(sx, sina), __fmul_rn(sy, cosa));
        const bool in =
            (fabsf(__fsub_rn(pz, cz)) <= hz) &&
            (lx > -hx) && (lx < hx) &&
            (ly > -hy) && (ly < hy);
        const unsigned bal = __ballot_sync(0xffffffffu, in);
        if (lane == 0) s_words[W] = bal;
    }
    __syncthreads();

    // ---- Phase 2: scan + ordered compaction ----
    unsigned w = s_words[tid];              // NWORDS == NT
    const int c = __popc(w);
    int incl = c;
    #pragma unroll
    for (int off = 1; off < 32; off <<= 1) {
        int v = __shfl_up_sync(0xffffffffu, incl, off);
        if (lane >= off) incl += v;
    }
    if (lane == 31) s_warpSum[wid] = incl;
    __syncthreads();
    if (wid == 0) {
        int v = (lane < 16) ? s_warpSum[lane] : 0;
        int iv = v;
        #pragma unroll
        for (int off = 1; off < 16; off <<= 1) {
            int t = __shfl_up_sync(0xffffffffu, iv, off);
            if (lane >= off) iv += t;
        }
        if (lane < 16) s_warpSum[lane] = iv - v;  // exclusive warp bases
        if (lane == 15) s_total = iv;
    }
    __syncthreads();

    int base = s_warpSum[wid] + (incl - c);
    const int word_pt = tid * 32;
    while (w) {
        const int bit = __ffs(w) - 1;
        w &= (w - 1);
        if (base < Sn) s_table[base] = word_pt + bit;
        base++;
    }
    __syncthreads();

    int cnt = s_total;
    if (cnt > Sn) cnt = Sn;

    // resolve wrap-around indices (one per output row)
    s_idx[tid] = (cnt > 0) ? s_table[tid % cnt] : -1;
    __syncthreads();

    // ---- Phase 3: warp-per-row gather + staged coalesced writes ----
    float* outbox = out + (size_t)bm * Sn * ROW;
    int p = 0;
    for (int r = wid; r < Sn; r += NWARP, p ^= 1) {
        float* sw = (float*)&s_stage[wid][p][0];
        const int idx = s_idx[r];
        float4 f = make_float4(0.f, 0.f, 0.f, 0.f);
        float pv = 0.f;
        if (idx >= 0) {
            f = fb4[(size_t)idx * (Cn / 4) + lane];          // LDG.128
            if (lane < 3) pv = pts[idx * 3 + lane];
        }
        ((float4*)sw)[lane] = f;                              // STS.128, conflict-free
        if (lane < 3) sw[128 + lane] = pv;
        __syncwarp();
        float* orow = outbox + (size_t)r * ROW;
        #pragma unroll
        for (int k = 0; k < 5; k++) {
            const int pos = k * 32 + lane;
            if (pos < ROW) {
                const int j = (pos < 3) ? (128 + pos) : (pos - 3);
                orow[pos] = sw[j];                            // coalesced STG.32
            }
        }
        // next iteration writes the other buffer; the syncwarp above orders
        // this iteration's reads before the same buffer's next stores
    }

    // ---- empty flag ----
    if (write_flags && tid == 0) {
        out[(size_t)Bn * Mn * Sn * ROW + bm] = (cnt == 0) ? 1.0f : 0.0f;
    }
}

extern "C" void kernel_launch(void* const* d_in, const int* in_sizes, int n_in,
                              void* d_out, int out_size)
{
    const float* points = (const float*)d_in[0];   // (B, N, 3)
    const float* feats  = (const float*)d_in[1];   // (B, N, C)
    const float* boxes  = (const float*)d_in[2];   // (B, M, 7)
    float* out = (float*)d_out;

    const long long pooled = (long long)Bn * Mn * Sn * ROW;   // 34,340,864
    const int write_flags = ((long long)out_size >= pooled + (long long)Bn * Mn) ? 1 : 0;

    roipool_kernel<<<Bn * Mn, NT>>>(points, feats, boxes, out, write_flags);
}

// round 6
// speedup vs baseline: 1.7322x; 1.7322x over previous
#include <cuda_runtime.h>
#include <cuda_bf16.h>

// Problem constants (fixed for RoIPointPool3d_23845658427905)
#define Bn 4
#define Nn 16384
#define Mn 128
#define Cn 128
#define Sn 512
#define ROW (3 + Cn)          // 131 floats per pooled row
#define NWORDS (Nn / 32)      // 512 ballot words per box
#define NT 512                // threads per block (one block per box)
#define NWARP (NT / 32)       // 16

// Fused kernel: one block per (batch, box).
//  Phase 1: warp-parallel point-in-rotated-box ballots -> shared bitmask
//  Phase 2: block scan of popcounts -> first-come-ordered index compaction
//  Phase 3: source-major replication — load each unique in-box row ONCE into
//           registers, store to all wrap-around output rows (pure STG loop)
__global__ __launch_bounds__(NT, 3) void roipool_kernel(
    const float* __restrict__ points,   // (B, N, 3)
    const float* __restrict__ feats,    // (B, N, C)
    const float* __restrict__ boxes,    // (B, M, 7)
    float* __restrict__ out,            // (B, M, S, 131) [+ (B,M) flags]
    int write_flags)
{
    __shared__ unsigned s_words[NWORDS];    // in-box bitmask
    __shared__ int s_table[Sn];             // first min(cnt,S) in-box point indices
    __shared__ int s_warpSum[16];
    __shared__ int s_total;

    const int bm   = blockIdx.x;            // 0 .. B*M-1
    const int b    = bm >> 7;               // / M (M = 128)
    const int tid  = threadIdx.x;
    const int lane = tid & 31;
    const int wid  = tid >> 5;

    // ---- box parameters ----
    const float* box = boxes + bm * 7;
    const float cx = box[0];
    const float cy = box[1];
    const float dx = box[3], dy = box[4], dz = box[5];
    const float rz = box[6];
    const float cz = __fadd_rn(box[2], __fmul_rn(0.5f, dz));
    const float hx = __fmul_rn(0.5f, dx);
    const float hy = __fmul_rn(0.5f, dy);
    const float hz = __fmul_rn(0.5f, dz);
    const double nrz = -(double)rz;
    const float cosa = (float)cos(nrz);
    const float sina = (float)sin(nrz);

    const float* pts = points + (size_t)b * Nn * 3;
    const float* fb  = feats  + (size_t)b * Nn * Cn;

    // ---- Phase 1: ballots (no block syncs, pipelined) ----
    #pragma unroll 4
    for (int W = wid; W < NWORDS; W += NWARP) {
        const int i = W * 32 + lane;
        const float px = pts[i * 3 + 0];
        const float py = pts[i * 3 + 1];
        const float pz = pts[i * 3 + 2];
        const float sx = __fsub_rn(px, cx);
        const float sy = __fsub_rn(py, cy);
        const float lx = __fsub_rn(__fmul_rn(sx, cosa), __fmul_rn(sy, sina));
        const float ly = __fadd_rn(__fmul_rn(sx, sina), __fmul_rn(sy, cosa));
        const bool in =
            (fabsf(__fsub_rn(pz, cz)) <= hz) &&
            (lx > -hx) && (lx < hx) &&
            (ly > -hy) && (ly < hy);
        const unsigned bal = __ballot_sync(0xffffffffu, in);
        if (lane == 0) s_words[W] = bal;
    }
    __syncthreads();

    // ---- Phase 2: scan + ordered compaction ----
    unsigned w = s_words[tid];              // NWORDS == NT
    const int c = __popc(w);
    int incl = c;
    #pragma unroll
    for (int off = 1; off < 32; off <<= 1) {
        int v = __shfl_up_sync(0xffffffffu, incl, off);
        if (lane >= off) incl += v;
    }
    if (lane == 31) s_warpSum[wid] = incl;
    __syncthreads();
    if (wid == 0) {
        int v = (lane < 16) ? s_warpSum[lane] : 0;
        int iv = v;
        #pragma unroll
        for (int off = 1; off < 16; off <<= 1) {
            int t = __shfl_up_sync(0xffffffffu, iv, off);
            if (lane >= off) iv += t;
        }
        if (lane < 16) s_warpSum[lane] = iv - v;  // exclusive warp bases
        if (lane == 15) s_total = iv;
    }
    __syncthreads();

    int base = s_warpSum[wid] + (incl - c);
    const int word_pt = tid * 32;
    while (w) {
        const int bit = __ffs(w) - 1;
        w &= (w - 1);
        if (base < Sn) s_table[base] = word_pt + bit;
        base++;
    }
    __syncthreads();

    int cnt = s_total;
    if (cnt > Sn) cnt = Sn;                 // r % cnt only ever hits [0, min(cnt,S))

    // ---- Phase 3: source-major replication ----
    // Row register layout: v[k] = rowvalue[k*32 + lane], k = 0..4
    //   rowvalue[p] = p<3 ? pts[idx*3+p] : feats[idx*128 + p-3]
    float* outbox = out + (size_t)bm * Sn * ROW;

    if (cnt >= NWARP) {
        // enough unique sources to keep all 16 warps busy
        for (int j = wid; j < cnt; j += NWARP) {
            const int idx = s_table[j];
            const float* fr = fb + (size_t)idx * Cn;
            float v0 = (lane < 3) ? pts[idx * 3 + lane] : fr[lane - 3];
            float v1 = fr[32 + lane - 3];
            float v2 = fr[64 + lane - 3];
            float v3 = fr[96 + lane - 3];
            float v4 = (lane < 3) ? fr[125 + lane] : 0.0f;
            // replicate to all output rows r with r % cnt == j
            for (int r = j; r < Sn; r += cnt) {
                float* orow = outbox + (size_t)r * ROW;
                orow[lane]       = v0;
                orow[32 + lane]  = v1;
                orow[64 + lane]  = v2;
                orow[96 + lane]  = v3;
                if (lane < 3) orow[128 + lane] = v4;
            }
        }
    } else {
        // few sources (incl. cnt == 0): row-major, reload per row (L1-hot)
        for (int r = wid; r < Sn; r += NWARP) {
            float v0 = 0.f, v1 = 0.f, v2 = 0.f, v3 = 0.f, v4 = 0.f;
            if (cnt > 0) {
                const int idx = s_table[r % cnt];
                const float* fr = fb + (size_t)idx * Cn;
                v0 = (lane < 3) ? pts[idx * 3 + lane] : fr[lane - 3];
                v1 = fr[32 + lane - 3];
                v2 = fr[64 + lane - 3];
                v3 = fr[96 + lane - 3];
                v4 = (lane < 3) ? fr[125 + lane] : 0.0f;
            }
            float* orow = outbox + (size_t)r * ROW;
            orow[lane]       = v0;
            orow[32 + lane]  = v1;
            orow[64 + lane]  = v2;
            orow[96 + lane]  = v3;
            if (lane < 3) orow[128 + lane] = v4;
        }
    }

    // ---- empty flag ----
    if (write_flags && tid == 0) {
        out[(size_t)Bn * Mn * Sn * ROW + bm] = (cnt == 0) ? 1.0f : 0.0f;
    }
}

extern "C" void kernel_launch(void* const* d_in, const int* in_sizes, int n_in,
                              void* d_out, int out_size)
{
    const float* points = (const float*)d_in[0];   // (B, N, 3)
    const float* feats  = (const float*)d_in[1];   // (B, N, C)
    const float* boxes  = (const float*)d_in[2];   // (B, M, 7)
    float* out = (float*)d_out;

    const long long pooled = (long long)Bn * Mn * Sn * ROW;   // 34,340,864
    const int write_flags = ((long long)out_size >= pooled + (long long)Bn * Mn) ? 1 : 0;

    roipool_kernel<<<Bn * Mn, NT>>>(points, feats, boxes, out, write_flags);
}